// round 15
// baseline (speedup 1.0000x reference)
// R14: (1) fg+h merged into ONE GEMM launch (MODE 8, stacked 640-row B,
// grid (5,128); epilogue branches fg-norms vs h-transposed on blockIdx.x).
// (2) o-GEMM 3-stage cp.async AND 2 CTAs/SM (2x110.6KB = 216KB < 228KB smem).
// Arithmetic bit-identical to R13.
#include <cuda_runtime.h>
#include <cuda_bf16.h>
#include <cstdint>
#include <math.h>

#define B_    4
#define N_    4096
#define F_    512
#define C_    64
#define M_TOT (B_ * N_)   // 16384

// ---------------- scratch (allocation-free) ----------------
__device__ float g_fg[(size_t)M_TOT * 128];              //  8 MiB [f|g] tf32
__device__ __nv_bfloat16 g_hT[(size_t)M_TOT * F_];       // 16 MiB, [B][F][N] bf16
__device__ __nv_bfloat16 g_p[(size_t)M_TOT * N_];        // 128 MiB exp(bf16)
__device__ float g_part[(size_t)32 * M_TOT];             //  2 MiB partial rowsums
__device__ float g_rs[M_TOT];
__device__ float g_normf[M_TOT];
__device__ int   g_maxg[B_];
__device__ float g_bias[640];                            // [bf|bg|bh]
__device__ float g_wB[640 * F_];                         // [WfT;WgT;WhT] K-major

// ---------------- helpers ----------------
__device__ __forceinline__ float tf32r(float x) {
    uint32_t u;
    asm("cvt.rna.tf32.f32 %0, %1;" : "=r"(u) : "f"(x));
    return __uint_as_float(u);
}
__device__ __forceinline__ uint32_t smem_u32(const void* p) {
    uint32_t a;
    asm("{ .reg .u64 t; cvta.to.shared.u64 t, %1; cvt.u32.u64 %0, t; }" : "=r"(a) : "l"(p));
    return a;
}
#define CP16(dst, src) \
    asm volatile("cp.async.ca.shared.global [%0], [%1], 16;" :: "r"(dst), "l"(src))
#define CP_COMMIT() asm volatile("cp.async.commit_group;" ::: "memory")
#define CP_WAIT2()  asm volatile("cp.async.wait_group 2;" ::: "memory")
#define CP_WAIT1()  asm volatile("cp.async.wait_group 1;" ::: "memory")
#define CP_WAIT0()  asm volatile("cp.async.wait_group 0;" ::: "memory")
#define LDSM_X4(r0, r1, r2, r3, addr) \
    asm volatile("ldmatrix.sync.aligned.m8n8.x4.shared.b16 {%0,%1,%2,%3}, [%4];" \
        : "=r"(r0), "=r"(r1), "=r"(r2), "=r"(r3) : "r"(addr))

__device__ __forceinline__ void mma_tf32(float* d, const float* a, const float* b) {
    asm volatile(
        "mma.sync.aligned.m16n8k8.row.col.f32.tf32.tf32.f32 "
        "{%0,%1,%2,%3}, {%4,%5,%6,%7}, {%8,%9}, {%0,%1,%2,%3};"
        : "+f"(d[0]), "+f"(d[1]), "+f"(d[2]), "+f"(d[3])
        : "r"(__float_as_uint(a[0])), "r"(__float_as_uint(a[1])),
          "r"(__float_as_uint(a[2])), "r"(__float_as_uint(a[3])),
          "r"(__float_as_uint(b[0])), "r"(__float_as_uint(b[1])));
}
__device__ __forceinline__ void mma_bf16(float* d, const uint32_t* a, const uint32_t* b) {
    asm volatile(
        "mma.sync.aligned.m16n8k16.row.col.f32.bf16.bf16.f32 "
        "{%0,%1,%2,%3}, {%4,%5,%6,%7}, {%8,%9}, {%0,%1,%2,%3};"
        : "+f"(d[0]), "+f"(d[1]), "+f"(d[2]), "+f"(d[3])
        : "r"(a[0]), "r"(a[1]), "r"(a[2]), "r"(a[3]), "r"(b[0]), "r"(b[1]));
}

// ---------------------------------------------------------------------------
// tf32 GEMM: acc = A[M,K-ish] @ B^T tiles. BK=32, LDS=36, 2-stage cp.async,
// 2 CTAs/SM. RA: round A frags to tf32 in-register.
// MODE 8 (merged projections): A=V [16384,512], B=stacked [640,512].
//   blockIdx.x==0 -> fg: fp32 tf32r(relu(acc+bias)) to C (stride 128) + fused
//   row norms (normf + 1 atomicMax/CTA). Else -> h: bf16 relu(acc+bias)
//   written transposed per batch to hT.
// MODE 6 (scores): p = bf16(exp(acc - normf[row]*maxg[bz])); partial rowsums.
// ---------------------------------------------------------------------------
template <int NT, int MODE, bool RA>
__global__ __launch_bounds__(256, 2) void gemm_tf32(
    const float* __restrict__ A, const float* __restrict__ Bm, float* __restrict__ C,
    __nv_bfloat16* __restrict__ hT,
    int M, int K, int ldA, int ldB,
    const float* __restrict__ bias,
    const float* __restrict__ normf, int* __restrict__ maxg,
    float* __restrict__ partial,
    long sA, long sB, long sC)
{
    constexpr int BK = 32, LDS = 36;
    constexpr int WN_WARPS = 4, WM_WARPS = 2;
    constexpr int WMT = 64;
    constexpr int WNT = NT / WN_WARPS;
    constexpr int MF = 4, NF = WNT / 8;
    constexpr int ASZ = 128 * LDS, BUF = ASZ + NT * LDS;
    constexpr int LB = NT / 32;

    extern __shared__ float sm[];
    const int tid = threadIdx.x, wid = tid >> 5, lane = tid & 31;
    const int lr = lane >> 2, lc = lane & 3;
    const int bz = blockIdx.z;

    A  += (size_t)bz * sA;
    Bm += (size_t)bz * sB;

    const int m0 = blockIdx.y * 128, n0 = blockIdx.x * NT;
    const int wm = wid % WM_WARPS, wn = wid / WM_WARPS;
    const uint32_t sbase = smem_u32(sm);

    float acc[MF][NF][4];
#pragma unroll
    for (int i = 0; i < MF; i++)
#pragma unroll
        for (int j = 0; j < NF; j++)
#pragma unroll
            for (int r = 0; r < 4; r++) acc[i][j][r] = 0.f;

    auto stage = [&](int k0, int buf) {
#pragma unroll
        for (int l = 0; l < 4; l++) {                 // A: 128 rows x 32 floats
            int idx = tid + l * 256;
            int r = idx >> 3, q = idx & 7;
            CP16(sbase + (uint32_t)(buf * BUF + r * LDS + q * 4) * 4,
                 A + (size_t)(m0 + r) * ldA + k0 + q * 4);
        }
#pragma unroll
        for (int l = 0; l < LB; l++) {                // B: NT rows x 32 floats
            int idx = tid + l * 256;
            int r = idx >> 3, q = idx & 7;
            CP16(sbase + (uint32_t)(buf * BUF + ASZ + r * LDS + q * 4) * 4,
                 Bm + (size_t)(n0 + r) * ldB + k0 + q * 4);
        }
        CP_COMMIT();
    };

    const int T = K / BK;
    stage(0, 0);
    for (int t = 0; t < T; t++) {
        if (t + 1 < T) { stage((t + 1) * BK, (t + 1) & 1); CP_WAIT1(); }
        else            { CP_WAIT0(); }
        __syncthreads();

        const float* As = sm + (t & 1) * BUF;
        const float* Bs = As + ASZ;
#pragma unroll
        for (int ks = 0; ks < BK / 8; ks++) {
            const int kk = ks * 8 + lc;
            float a[MF][4], b[NF][2];
#pragma unroll
            for (int mf = 0; mf < MF; mf++) {
                const int r0 = (wm * WMT + mf * 16 + lr) * LDS;
                a[mf][0] = As[r0 + kk];
                a[mf][1] = As[r0 + 8 * LDS + kk];
                a[mf][2] = As[r0 + kk + 4];
                a[mf][3] = As[r0 + 8 * LDS + kk + 4];
                if (RA) {
#pragma unroll
                    for (int r = 0; r < 4; r++) a[mf][r] = tf32r(a[mf][r]);
                }
            }
#pragma unroll
            for (int nf = 0; nf < NF; nf++) {
                const int r0 = (wn * WNT + nf * 8 + lr) * LDS;
                b[nf][0] = Bs[r0 + kk];
                b[nf][1] = Bs[r0 + kk + 4];
            }
#pragma unroll
            for (int mf = 0; mf < MF; mf++)
#pragma unroll
                for (int nf = 0; nf < NF; nf++)
                    mma_tf32(acc[mf][nf], a[mf], b[nf]);
        }
        __syncthreads();
    }

    const int mb = m0 + wm * WMT, nb = n0 + wn * WNT;

    if (MODE == 8) {
        if (blockIdx.x == 0) {
            // fg: fp32 tf32r(relu(acc+bias)) stores (row stride 128) + norms.
            float* spart = sm;
#pragma unroll
            for (int mf = 0; mf < MF; mf++) {
                const int gr0 = mb + mf * 16 + lr, gr1 = gr0 + 8;
                float ss0 = 0.f, ss1 = 0.f;
#pragma unroll
                for (int nf = 0; nf < NF; nf++) {
                    const int gc = nb + nf * 8 + 2 * lc;
                    const float* d = acc[mf][nf];
                    float v0 = fmaxf(d[0] + bias[gc], 0.f);
                    float v1 = fmaxf(d[1] + bias[gc + 1], 0.f);
                    float v2 = fmaxf(d[2] + bias[gc], 0.f);
                    float v3 = fmaxf(d[3] + bias[gc + 1], 0.f);
                    *reinterpret_cast<float2*>(&C[(size_t)gr0 * 128 + gc]) =
                        make_float2(tf32r(v0), tf32r(v1));
                    *reinterpret_cast<float2*>(&C[(size_t)gr1 * 128 + gc]) =
                        make_float2(tf32r(v2), tf32r(v3));
                    ss0 += v0 * v0 + v1 * v1;
                    ss1 += v2 * v2 + v3 * v3;
                }
                ss0 += __shfl_xor_sync(~0u, ss0, 1); ss0 += __shfl_xor_sync(~0u, ss0, 2);
                ss1 += __shfl_xor_sync(~0u, ss1, 1); ss1 += __shfl_xor_sync(~0u, ss1, 2);
                if (lc == 0) {
                    int rl0 = wm * WMT + mf * 16 + lr;
                    spart[wn * 128 + rl0]     = ss0;
                    spart[wn * 128 + rl0 + 8] = ss1;
                }
            }
            __syncthreads();
            if (tid < 128) {
                int row = m0 + tid;
                float sf = spart[tid] + spart[128 + tid];          // f cols
                float sg = spart[256 + tid] + spart[384 + tid];    // g cols
                partial[row] = sqrtf(sf);
                spart[512 + tid] = sqrtf(sg);
            }
            __syncthreads();
            if (tid < 32) {
                float mg = fmaxf(fmaxf(spart[512 + tid],      spart[512 + tid + 32]),
                                 fmaxf(spart[512 + tid + 64], spart[512 + tid + 96]));
#pragma unroll
                for (int o = 16; o; o >>= 1) mg = fmaxf(mg, __shfl_xor_sync(~0u, mg, o));
                if (tid == 0) atomicMax(&maxg[m0 >> 12], __float_as_int(mg));
            }
        } else {
            // h: bf16 relu(acc+bias), transposed per batch into hT[B][F][N].
#pragma unroll
            for (int mf = 0; mf < MF; mf++) {
                const int gr0 = mb + mf * 16 + lr, gr1 = gr0 + 8;
#pragma unroll
                for (int nf = 0; nf < NF; nf++) {
                    const int gc = nb + nf * 8 + 2 * lc;   // 128..639
                    const int gch = gc - 128;              // h column 0..511
                    const float* d = acc[mf][nf];
                    float v0 = fmaxf(d[0] + bias[gc], 0.f);
                    float v1 = fmaxf(d[1] + bias[gc + 1], 0.f);
                    float v2 = fmaxf(d[2] + bias[gc], 0.f);
                    float v3 = fmaxf(d[3] + bias[gc + 1], 0.f);
                    size_t b0 = ((size_t)(gr0 >> 12) * F_);
                    size_t b1 = ((size_t)(gr1 >> 12) * F_);
                    hT[(b0 + gch)     * 4096 + (gr0 & 4095)] = __float2bfloat16_rn(v0);
                    hT[(b0 + gch + 1) * 4096 + (gr0 & 4095)] = __float2bfloat16_rn(v1);
                    hT[(b1 + gch)     * 4096 + (gr1 & 4095)] = __float2bfloat16_rn(v2);
                    hT[(b1 + gch + 1) * 4096 + (gr1 & 4095)] = __float2bfloat16_rn(v3);
                }
            }
        }
    } else {  // MODE 6
        __nv_bfloat16* Pb = (__nv_bfloat16*)C + (size_t)bz * sC;
        float* spart = sm;
        const float Mg = __int_as_float(maxg[bz]);
        const int grow_base = bz * 4096;
#pragma unroll
        for (int mf = 0; mf < MF; mf++) {
            const int gr0 = mb + mf * 16 + lr, gr1 = gr0 + 8;
            const float M0 = normf[grow_base + gr0] * Mg;
            const float M1 = normf[grow_base + gr1] * Mg;
            float s0 = 0.f, s1 = 0.f;
#pragma unroll
            for (int nf = 0; nf < NF; nf++) {
                const int gc = nb + nf * 8 + 2 * lc;
                const float* d = acc[mf][nf];
                float e0 = __expf(d[0] - M0), e1 = __expf(d[1] - M0);
                float e2 = __expf(d[2] - M1), e3 = __expf(d[3] - M1);
                __nv_bfloat162 h0 = __floats2bfloat162_rn(e0, e1);
                __nv_bfloat162 h1 = __floats2bfloat162_rn(e2, e3);
                *reinterpret_cast<uint32_t*>(&Pb[(size_t)gr0 * N_ + gc]) =
                    *reinterpret_cast<uint32_t*>(&h0);
                *reinterpret_cast<uint32_t*>(&Pb[(size_t)gr1 * N_ + gc]) =
                    *reinterpret_cast<uint32_t*>(&h1);
                s0 += e0 + e1;
                s1 += e2 + e3;
            }
            s0 += __shfl_xor_sync(~0u, s0, 1); s0 += __shfl_xor_sync(~0u, s0, 2);
            s1 += __shfl_xor_sync(~0u, s1, 1); s1 += __shfl_xor_sync(~0u, s1, 2);
            if (lc == 0) {
                int rl0 = wm * WMT + mf * 16 + lr;
                spart[wn * 128 + rl0]     = s0;
                spart[wn * 128 + rl0 + 8] = s1;
            }
        }
        __syncthreads();
        if (tid < 128) {
            float s = spart[tid] + spart[128 + tid] + spart[256 + tid] + spart[384 + tid];
            partial[(size_t)blockIdx.x * M_TOT + grow_base + m0 + tid] = s;
        }
    }
}

// ---------------------------------------------------------------------------
// bf16 GEMM (final): out = gamma[n]*((p @ hT^T)/rowsum[m]) + V.
// BK=64 halfs, 3-stage cp.async AND 2 CTAs/SM (216KB total); ldmatrix loads.
// ---------------------------------------------------------------------------
__global__ __launch_bounds__(256, 2) void gemm_bf16_o(
    const __nv_bfloat16* __restrict__ A, const __nv_bfloat16* __restrict__ Bm,
    float* __restrict__ C, int M, int Nfull, int K,
    const float* __restrict__ gamma, const float* __restrict__ vres,
    const float* __restrict__ rowsum, long sA, long sB, long sC, long sV)
{
    constexpr int NT = 128, LDA = 36;                 // uint32 pairs per row
    constexpr int BKH = 64;
    constexpr int WMT = 64, WNT = 32, MF = 4, NF = 4;
    constexpr int ASZ = 128 * LDA, BUF = ASZ + NT * LDA;   // uint32 units

    extern __shared__ uint32_t smu[];
    const int tid = threadIdx.x, wid = tid >> 5, lane = tid & 31;
    const int lr = lane >> 2, lc = lane & 3;
    const int bz = blockIdx.z;

    A  += (size_t)bz * sA;
    Bm += (size_t)bz * sB;
    float* Cb = C + (size_t)bz * sC;
    const float* vres_b = vres + (size_t)bz * sV;
    const float* rs_b   = rowsum + (size_t)bz * M;

    const int m0 = blockIdx.y * 128, n0 = blockIdx.x * NT;
    const int wm = wid & 1, wn = wid >> 1;
    const uint32_t sbase = smem_u32(smu);

    const int a_row = wm * WMT + (lane & 15);
    const uint32_t a_off0 = (uint32_t)a_row * (LDA * 4) + ((lane >> 4) * 16);
    const int b_row = wn * WNT + (((lane >> 4) & 1) * 8) + (lane & 7);
    const uint32_t b_off0 = (uint32_t)(ASZ * 4) + (uint32_t)b_row * (LDA * 4) +
                            (((lane >> 3) & 1) * 16);

    float acc[MF][NF][4];
#pragma unroll
    for (int i = 0; i < MF; i++)
#pragma unroll
        for (int j = 0; j < NF; j++)
#pragma unroll
            for (int r = 0; r < 4; r++) acc[i][j][r] = 0.f;

    auto stage = [&](int k0, int buf) {
#pragma unroll
        for (int l = 0; l < 4; l++) {
            int idx = tid + l * 256;
            int r = idx >> 3, q = idx & 7;
            CP16(sbase + (uint32_t)(buf * BUF + r * LDA + q * 4) * 4,
                 A + (size_t)(m0 + r) * K + k0 + q * 8);
        }
#pragma unroll
        for (int l = 0; l < 4; l++) {
            int idx = tid + l * 256;
            int r = idx >> 3, q = idx & 7;
            CP16(sbase + (uint32_t)(buf * BUF + ASZ + r * LDA + q * 4) * 4,
                 Bm + (size_t)(n0 + r) * K + k0 + q * 8);
        }
        CP_COMMIT();
    };

    const int T = K / BKH;
    stage(0, 0);
    stage(BKH, 1);
    for (int t = 0; t < T; t++) {
        if (t + 2 < T)      { stage((t + 2) * BKH, (t + 2) % 3); CP_WAIT2(); }
        else if (t + 1 < T) { CP_WAIT1(); }
        else                { CP_WAIT0(); }
        __syncthreads();

        const uint32_t bufbase = sbase + (uint32_t)((t % 3) * BUF) * 4;
#pragma unroll
        for (int ks = 0; ks < 4; ks++) {      // 4 k16 steps per tile
            uint32_t a[MF][4], b[NF][2];
#pragma unroll
            for (int mf = 0; mf < MF; mf++)
                LDSM_X4(a[mf][0], a[mf][1], a[mf][2], a[mf][3],
                        bufbase + a_off0 + (uint32_t)(mf * 16 * LDA * 4) + ks * 32);
#pragma unroll
            for (int np = 0; np < 2; np++)
                LDSM_X4(b[2 * np][0], b[2 * np][1], b[2 * np + 1][0], b[2 * np + 1][1],
                        bufbase + b_off0 + (uint32_t)(np * 16 * LDA * 4) + ks * 32);
#pragma unroll
            for (int mf = 0; mf < MF; mf++)
#pragma unroll
                for (int nf = 0; nf < NF; nf++)
                    mma_bf16(acc[mf][nf], a[mf], b[nf]);
        }
        __syncthreads();
    }

    const int mb = m0 + wm * WMT, nb = n0 + wn * WNT;
#pragma unroll
    for (int mf = 0; mf < MF; mf++) {
        const int gr0 = mb + mf * 16 + lr, gr1 = gr0 + 8;
        const float inv0 = 1.f / rs_b[gr0], inv1 = 1.f / rs_b[gr1];
#pragma unroll
        for (int nf = 0; nf < NF; nf++) {
            const int gc = nb + nf * 8 + 2 * lc;
            const float* d = acc[mf][nf];
            float2 vr0 = *reinterpret_cast<const float2*>(&vres_b[(size_t)gr0 * Nfull + gc]);
            float2 vr1 = *reinterpret_cast<const float2*>(&vres_b[(size_t)gr1 * Nfull + gc]);
            float2 gg  = *reinterpret_cast<const float2*>(&gamma[gc]);
            *reinterpret_cast<float2*>(&Cb[(size_t)gr0 * Nfull + gc]) =
                make_float2(fmaf(gg.x, d[0] * inv0, vr0.x), fmaf(gg.y, d[1] * inv0, vr0.y));
            *reinterpret_cast<float2*>(&Cb[(size_t)gr1 * Nfull + gc]) =
                make_float2(fmaf(gg.x, d[2] * inv1, vr1.x), fmaf(gg.y, d[3] * inv1, vr1.y));
        }
    }
}

// ---------------------------------------------------------------------------
// Small kernels
// ---------------------------------------------------------------------------
__global__ void transpose_k(const float* __restrict__ in, float* __restrict__ out,
                            int R, int Ccols)
{
    __shared__ float t[32][33];
    const int c0 = blockIdx.x * 32, r0 = blockIdx.y * 32;
    const int x = threadIdx.x, y = threadIdx.y;
#pragma unroll
    for (int i = 0; i < 32; i += 8)
        t[y + i][x] = in[(size_t)(r0 + y + i) * Ccols + c0 + x];
    __syncthreads();
#pragma unroll
    for (int i = 0; i < 32; i += 8)
        out[(size_t)(c0 + y + i) * R + r0 + x] = tf32r(t[x][y + i]);
}

// Transpose two [F,C] weights into stacked slabs of out in one launch.
__global__ void transpose2_k(const float* __restrict__ inA, const float* __restrict__ inB,
                             float* __restrict__ out, int R, int Ccols)
{
    __shared__ float t[32][33];
    const float* in = blockIdx.z ? inB : inA;
    float* o = out + (size_t)blockIdx.z * Ccols * R;
    const int c0 = blockIdx.x * 32, r0 = blockIdx.y * 32;
    const int x = threadIdx.x, y = threadIdx.y;
#pragma unroll
    for (int i = 0; i < 32; i += 8)
        t[y + i][x] = in[(size_t)(r0 + y + i) * Ccols + c0 + x];
    __syncthreads();
#pragma unroll
    for (int i = 0; i < 32; i += 8)
        o[(size_t)(c0 + y + i) * R + r0 + x] = tf32r(t[x][y + i]);
}

// stacked bias [bf|bg|bh] + maxg zero
__global__ void prep_k(const float* __restrict__ a, const float* __restrict__ b,
                       const float* __restrict__ c, float* __restrict__ out,
                       int* __restrict__ mg)
{
    int t = blockIdx.x * 128 + threadIdx.x;   // 0..639
    out[t] = (t < 64) ? a[t] : (t < 128) ? b[t - 64] : c[t - 128];
    if (t < B_) mg[t] = 0;
}

__global__ __launch_bounds__(256) void reduce_rs_k(const float* __restrict__ partial,
                                                   float* __restrict__ rs)
{
    int i = blockIdx.x * 256 + threadIdx.x;
    float s = 0.f;
#pragma unroll
    for (int nt = 0; nt < 32; nt++) s += partial[(size_t)nt * M_TOT + i];
    rs[i] = s;
}

// ---------------------------------------------------------------------------
extern "C" void kernel_launch(void* const* d_in, const int* in_sizes, int n_in,
                              void* d_out, int out_size)
{
    const float* V  = (const float*)d_in[0];
    const float* Wf = (const float*)d_in[1];
    const float* bf = (const float*)d_in[2];
    const float* Wg = (const float*)d_in[3];
    const float* bg = (const float*)d_in[4];
    const float* Wh = (const float*)d_in[5];
    const float* bh = (const float*)d_in[6];
    const float* gm = (const float*)d_in[7];
    float* out = (float*)d_out;

    float *fgP, *partP, *rsP, *normfP, *biasP, *wB;
    int* maxgP;
    __nv_bfloat16 *hTP, *pP;
    cudaGetSymbolAddress((void**)&fgP,   g_fg);
    cudaGetSymbolAddress((void**)&hTP,   g_hT);
    cudaGetSymbolAddress((void**)&pP,    g_p);
    cudaGetSymbolAddress((void**)&partP, g_part);
    cudaGetSymbolAddress((void**)&rsP,   g_rs);
    cudaGetSymbolAddress((void**)&normfP,g_normf);
    cudaGetSymbolAddress((void**)&maxgP, g_maxg);
    cudaGetSymbolAddress((void**)&biasP, g_bias);
    cudaGetSymbolAddress((void**)&wB,    g_wB);

    const int SM_TF = 2 * (128 + 128) * 36 * 4;   // 73728 B
    const int SM_BF = 3 * (128 + 128) * 36 * 4;   // 110592 B (3-stage)

    cudaFuncSetAttribute(gemm_tf32<128, 8, true>,
                         cudaFuncAttributeMaxDynamicSharedMemorySize, SM_TF);
    cudaFuncSetAttribute(gemm_tf32<128, 6, false>,
                         cudaFuncAttributeMaxDynamicSharedMemorySize, SM_TF);
    cudaFuncSetAttribute(gemm_bf16_o,
                         cudaFuncAttributeMaxDynamicSharedMemorySize, SM_BF);

    dim3 blk(256);
    dim3 tb(32, 8);

    // Stacked B: [WfT; WgT] slabs 0,1 then WhT at row 128. Stacked bias.
    transpose2_k<<<dim3(C_ / 32, F_ / 32, 2), tb>>>(Wf, Wg, wB, F_, C_);
    transpose_k<<<dim3(F_ / 32, F_ / 32), tb>>>(Wh, wB + 128 * F_, F_, F_);
    prep_k<<<5, 128>>>(bf, bg, bh, biasP, maxgP);

    // Merged projections: fg (blockIdx.x==0, with norms) + hT (x=1..4)
    gemm_tf32<128, 8, true><<<dim3(5, 128, 1), blk, SM_TF>>>(
        V, wB, fgP, hTP, M_TOT, F_, F_, F_, biasP,
        nullptr, maxgP, normfP, 0, 0, 0);

    // scores + fused exp: p = bf16(exp(f@g^T - M_row)), partial rowsums
    gemm_tf32<128, 6, false><<<dim3(32, 32, B_), blk, SM_TF>>>(
        fgP, fgP + 64, (float*)pP, nullptr, N_, C_, 128, 128, nullptr,
        normfP, maxgP, partP,
        (long)N_ * 128, (long)N_ * 128, (long)N_ * N_);

    // rowsum = sum of 32 n-tile partials (deterministic)
    reduce_rs_k<<<M_TOT / 256, blk>>>(partP, rsP);

    // out = gamma * (p @ h / rowsum) + V
    gemm_bf16_o<<<dim3(4, 32, B_), blk, SM_BF>>>(
        pP, hTP, out, N_, F_, N_, gm, V, rsP,
        (long)N_ * N_, (long)F_ * N_, (long)N_ * F_, (long)N_ * F_);
}

// round 16
// speedup vs baseline: 1.1699x; 1.1699x over previous
// R15: REVERT R14 (both bundled changes regressed: MODE-8 merge spilled regs;
// 3-stage o-GEMM lost its 2nd CTA/SM). Base = R13 verbatim, plus ONE delta:
// reduce_rs_k folded into gemm_bf16_o's prologue (same nt-order fp32 sum ->
// bit-identical; computed into smem stash overlapping first cp.async stage).
#include <cuda_runtime.h>
#include <cuda_bf16.h>
#include <cstdint>
#include <math.h>

#define B_    4
#define N_    4096
#define F_    512
#define C_    64
#define M_TOT (B_ * N_)   // 16384

// ---------------- scratch (allocation-free) ----------------
__device__ float g_fg[(size_t)M_TOT * 128];              //  8 MiB [f|g] tf32
__device__ __nv_bfloat16 g_hT[(size_t)M_TOT * F_];       // 16 MiB, [B][F][N] bf16
__device__ __nv_bfloat16 g_p[(size_t)M_TOT * N_];        // 128 MiB exp(bf16)
__device__ float g_part[(size_t)32 * M_TOT];             //  2 MiB partial rowsums
__device__ float g_normf[M_TOT];
__device__ int   g_maxg[B_];
__device__ float g_bfg[128];
__device__ float g_wfgT[128 * F_];                       // stacked [WfT; WgT]
__device__ float g_whT[F_ * F_];

// ---------------- helpers ----------------
__device__ __forceinline__ float tf32r(float x) {
    uint32_t u;
    asm("cvt.rna.tf32.f32 %0, %1;" : "=r"(u) : "f"(x));
    return __uint_as_float(u);
}
__device__ __forceinline__ uint32_t smem_u32(const void* p) {
    uint32_t a;
    asm("{ .reg .u64 t; cvta.to.shared.u64 t, %1; cvt.u32.u64 %0, t; }" : "=r"(a) : "l"(p));
    return a;
}
#define CP16(dst, src) \
    asm volatile("cp.async.ca.shared.global [%0], [%1], 16;" :: "r"(dst), "l"(src))
#define CP_COMMIT() asm volatile("cp.async.commit_group;" ::: "memory")
#define CP_WAIT1()  asm volatile("cp.async.wait_group 1;" ::: "memory")
#define CP_WAIT0()  asm volatile("cp.async.wait_group 0;" ::: "memory")
#define LDSM_X4(r0, r1, r2, r3, addr) \
    asm volatile("ldmatrix.sync.aligned.m8n8.x4.shared.b16 {%0,%1,%2,%3}, [%4];" \
        : "=r"(r0), "=r"(r1), "=r"(r2), "=r"(r3) : "r"(addr))

__device__ __forceinline__ void mma_tf32(float* d, const float* a, const float* b) {
    asm volatile(
        "mma.sync.aligned.m16n8k8.row.col.f32.tf32.tf32.f32 "
        "{%0,%1,%2,%3}, {%4,%5,%6,%7}, {%8,%9}, {%0,%1,%2,%3};"
        : "+f"(d[0]), "+f"(d[1]), "+f"(d[2]), "+f"(d[3])
        : "r"(__float_as_uint(a[0])), "r"(__float_as_uint(a[1])),
          "r"(__float_as_uint(a[2])), "r"(__float_as_uint(a[3])),
          "r"(__float_as_uint(b[0])), "r"(__float_as_uint(b[1])));
}
__device__ __forceinline__ void mma_bf16(float* d, const uint32_t* a, const uint32_t* b) {
    asm volatile(
        "mma.sync.aligned.m16n8k16.row.col.f32.bf16.bf16.f32 "
        "{%0,%1,%2,%3}, {%4,%5,%6,%7}, {%8,%9}, {%0,%1,%2,%3};"
        : "+f"(d[0]), "+f"(d[1]), "+f"(d[2]), "+f"(d[3])
        : "r"(a[0]), "r"(a[1]), "r"(a[2]), "r"(a[3]), "r"(b[0]), "r"(b[1]));
}

// ---------------------------------------------------------------------------
// tf32 GEMM: C[M, Nfull] = A[M,K] @ B^T, B stored [Nfull rows, K] with row
// stride ldB; A row stride ldA. BK=32, LDS=36 floats, 2-stage cp.async,
// 2 CTAs/SM. RA: round A frags to tf32 in-register.
// MODE 5: bf16 relu(acc+bias) written transposed per batch (h path).
// MODE 6: p = bf16(exp(acc - normf[row]*maxg[bz])); partial rowsums out.
// MODE 7: fp32 tf32r(relu(acc+bias)) -> C, PLUS fused row norms:
//         partial[row] = ||f_row||, atomicMax(maxg[batch], max||g_row||) 1/CTA.
// ---------------------------------------------------------------------------
template <int NT, int MODE, bool RA>
__global__ __launch_bounds__(256, 2) void gemm_tf32(
    const float* __restrict__ A, const float* __restrict__ Bm, float* __restrict__ C,
    int M, int Nfull, int K, int ldA, int ldB,
    const float* __restrict__ bias,
    const float* __restrict__ normf, int* __restrict__ maxg,
    float* __restrict__ partial,
    long sA, long sB, long sC)
{
    constexpr int BK = 32, LDS = 36;
    constexpr int WN_WARPS = 4, WM_WARPS = 2;
    constexpr int WMT = 64;
    constexpr int WNT = NT / WN_WARPS;
    constexpr int MF = 4, NF = WNT / 8;
    constexpr int ASZ = 128 * LDS, BUF = ASZ + NT * LDS;
    constexpr int LB = NT / 32;

    extern __shared__ float sm[];
    const int tid = threadIdx.x, wid = tid >> 5, lane = tid & 31;
    const int lr = lane >> 2, lc = lane & 3;
    const int bz = blockIdx.z;

    A  += (size_t)bz * sA;
    Bm += (size_t)bz * sB;
    float* Cb = C;
    if (MODE == 7) Cb = C + (size_t)bz * sC;

    const int m0 = blockIdx.y * 128, n0 = blockIdx.x * NT;
    const int wm = wid % WM_WARPS, wn = wid / WM_WARPS;
    const uint32_t sbase = smem_u32(sm);

    float acc[MF][NF][4];
#pragma unroll
    for (int i = 0; i < MF; i++)
#pragma unroll
        for (int j = 0; j < NF; j++)
#pragma unroll
            for (int r = 0; r < 4; r++) acc[i][j][r] = 0.f;

    auto stage = [&](int k0, int buf) {
#pragma unroll
        for (int l = 0; l < 4; l++) {                 // A: 128 rows x 32 floats
            int idx = tid + l * 256;
            int r = idx >> 3, q = idx & 7;
            CP16(sbase + (uint32_t)(buf * BUF + r * LDS + q * 4) * 4,
                 A + (size_t)(m0 + r) * ldA + k0 + q * 4);
        }
#pragma unroll
        for (int l = 0; l < LB; l++) {                // B: NT rows x 32 floats
            int idx = tid + l * 256;
            int r = idx >> 3, q = idx & 7;
            CP16(sbase + (uint32_t)(buf * BUF + ASZ + r * LDS + q * 4) * 4,
                 Bm + (size_t)(n0 + r) * ldB + k0 + q * 4);
        }
        CP_COMMIT();
    };

    const int T = K / BK;
    stage(0, 0);
    for (int t = 0; t < T; t++) {
        if (t + 1 < T) { stage((t + 1) * BK, (t + 1) & 1); CP_WAIT1(); }
        else            { CP_WAIT0(); }
        __syncthreads();

        const float* As = sm + (t & 1) * BUF;
        const float* Bs = As + ASZ;
#pragma unroll
        for (int ks = 0; ks < BK / 8; ks++) {
            const int kk = ks * 8 + lc;
            float a[MF][4], b[NF][2];
#pragma unroll
            for (int mf = 0; mf < MF; mf++) {
                const int r0 = (wm * WMT + mf * 16 + lr) * LDS;
                a[mf][0] = As[r0 + kk];
                a[mf][1] = As[r0 + 8 * LDS + kk];
                a[mf][2] = As[r0 + kk + 4];
                a[mf][3] = As[r0 + 8 * LDS + kk + 4];
                if (RA) {
#pragma unroll
                    for (int r = 0; r < 4; r++) a[mf][r] = tf32r(a[mf][r]);
                }
            }
#pragma unroll
            for (int nf = 0; nf < NF; nf++) {
                const int r0 = (wn * WNT + nf * 8 + lr) * LDS;
                b[nf][0] = Bs[r0 + kk];
                b[nf][1] = Bs[r0 + kk + 4];
            }
#pragma unroll
            for (int mf = 0; mf < MF; mf++)
#pragma unroll
                for (int nf = 0; nf < NF; nf++)
                    mma_tf32(acc[mf][nf], a[mf], b[nf]);
        }
        __syncthreads();
    }

    const int mb = m0 + wm * WMT, nb = n0 + wn * WNT;

    if (MODE == 7) {
        // fp32 tf32r(relu(acc+bias)) stores + fused row-norm reduction.
        float* spart = sm;                    // reuse (all smem reads done)
#pragma unroll
        for (int mf = 0; mf < MF; mf++) {
            const int gr0 = mb + mf * 16 + lr, gr1 = gr0 + 8;
            float ss0 = 0.f, ss1 = 0.f;       // sumsq of this warp's col block
#pragma unroll
            for (int nf = 0; nf < NF; nf++) {
                const int gc = nb + nf * 8 + 2 * lc;
                const float* d = acc[mf][nf];
                float v0 = fmaxf(d[0] + bias[gc], 0.f);
                float v1 = fmaxf(d[1] + bias[gc + 1], 0.f);
                float v2 = fmaxf(d[2] + bias[gc], 0.f);
                float v3 = fmaxf(d[3] + bias[gc + 1], 0.f);
                *reinterpret_cast<float2*>(&Cb[(size_t)gr0 * Nfull + gc]) =
                    make_float2(tf32r(v0), tf32r(v1));
                *reinterpret_cast<float2*>(&Cb[(size_t)gr1 * Nfull + gc]) =
                    make_float2(tf32r(v2), tf32r(v3));
                ss0 += v0 * v0 + v1 * v1;
                ss1 += v2 * v2 + v3 * v3;
            }
            ss0 += __shfl_xor_sync(~0u, ss0, 1); ss0 += __shfl_xor_sync(~0u, ss0, 2);
            ss1 += __shfl_xor_sync(~0u, ss1, 1); ss1 += __shfl_xor_sync(~0u, ss1, 2);
            if (lc == 0) {
                int rl0 = wm * WMT + mf * 16 + lr;
                spart[wn * 128 + rl0]     = ss0;
                spart[wn * 128 + rl0 + 8] = ss1;
            }
        }
        __syncthreads();
        if (tid < 128) {
            int row = m0 + tid;               // grid (1,128): full coverage
            float sf = spart[tid] + spart[128 + tid];          // wn 0,1 = f cols
            float sg = spart[256 + tid] + spart[384 + tid];    // wn 2,3 = g cols
            partial[row] = sqrtf(sf);
            spart[512 + tid] = sqrtf(sg);     // stage for block max-reduce
        }
        __syncthreads();
        if (tid < 32) {                       // block max over 128, 1 atomic/CTA
            float mg = fmaxf(fmaxf(spart[512 + tid],       spart[512 + tid + 32]),
                             fmaxf(spart[512 + tid + 64],  spart[512 + tid + 96]));
#pragma unroll
            for (int o = 16; o; o >>= 1) mg = fmaxf(mg, __shfl_xor_sync(~0u, mg, o));
            if (tid == 0) atomicMax(&maxg[m0 >> 12], __float_as_int(mg));
        }
    } else if (MODE == 5) {
        __nv_bfloat16* Ct = (__nv_bfloat16*)C;
#pragma unroll
        for (int mf = 0; mf < MF; mf++) {
            const int gr0 = mb + mf * 16 + lr, gr1 = gr0 + 8;
#pragma unroll
            for (int nf = 0; nf < NF; nf++) {
                const int gc = nb + nf * 8 + 2 * lc;
                const float* d = acc[mf][nf];
                float v0 = fmaxf(d[0] + bias[gc], 0.f);
                float v1 = fmaxf(d[1] + bias[gc + 1], 0.f);
                float v2 = fmaxf(d[2] + bias[gc], 0.f);
                float v3 = fmaxf(d[3] + bias[gc + 1], 0.f);
                size_t b0 = ((size_t)(gr0 >> 12) * Nfull);
                size_t b1 = ((size_t)(gr1 >> 12) * Nfull);
                Ct[(b0 + gc)     * 4096 + (gr0 & 4095)] = __float2bfloat16_rn(v0);
                Ct[(b0 + gc + 1) * 4096 + (gr0 & 4095)] = __float2bfloat16_rn(v1);
                Ct[(b1 + gc)     * 4096 + (gr1 & 4095)] = __float2bfloat16_rn(v2);
                Ct[(b1 + gc + 1) * 4096 + (gr1 & 4095)] = __float2bfloat16_rn(v3);
            }
        }
    } else {  // MODE 6
        __nv_bfloat16* Pb = (__nv_bfloat16*)C + (size_t)bz * sC;
        float* spart = sm;                    // reuse smem (all reads done)
        const float Mg = __int_as_float(maxg[bz]);
        const int grow_base = bz * 4096;
#pragma unroll
        for (int mf = 0; mf < MF; mf++) {
            const int gr0 = mb + mf * 16 + lr, gr1 = gr0 + 8;
            const float M0 = normf[grow_base + gr0] * Mg;
            const float M1 = normf[grow_base + gr1] * Mg;
            float s0 = 0.f, s1 = 0.f;
#pragma unroll
            for (int nf = 0; nf < NF; nf++) {
                const int gc = nb + nf * 8 + 2 * lc;
                const float* d = acc[mf][nf];
                float e0 = __expf(d[0] - M0), e1 = __expf(d[1] - M0);
                float e2 = __expf(d[2] - M1), e3 = __expf(d[3] - M1);
                __nv_bfloat162 h0 = __floats2bfloat162_rn(e0, e1);
                __nv_bfloat162 h1 = __floats2bfloat162_rn(e2, e3);
                *reinterpret_cast<uint32_t*>(&Pb[(size_t)gr0 * Nfull + gc]) =
                    *reinterpret_cast<uint32_t*>(&h0);
                *reinterpret_cast<uint32_t*>(&Pb[(size_t)gr1 * Nfull + gc]) =
                    *reinterpret_cast<uint32_t*>(&h1);
                s0 += e0 + e1;
                s1 += e2 + e3;
            }
            s0 += __shfl_xor_sync(~0u, s0, 1); s0 += __shfl_xor_sync(~0u, s0, 2);
            s1 += __shfl_xor_sync(~0u, s1, 1); s1 += __shfl_xor_sync(~0u, s1, 2);
            if (lc == 0) {
                int rl0 = wm * WMT + mf * 16 + lr;
                spart[wn * 128 + rl0]     = s0;
                spart[wn * 128 + rl0 + 8] = s1;
            }
        }
        __syncthreads();
        if (tid < 128) {
            float s = spart[tid] + spart[128 + tid] + spart[256 + tid] + spart[384 + tid];
            partial[(size_t)blockIdx.x * M_TOT + grow_base + m0 + tid] = s;
        }
    }
}

// ---------------------------------------------------------------------------
// bf16 GEMM (final): out = gamma[n]*((p @ hT^T)/rowsum[m]) + V.
// BK=64 halfs, 2-stage cp.async, 2 CTAs/SM; ldmatrix fragment loads.
// Rowsum computed in-prologue from the 32 n-tile partials (same nt order as
// the old reduce_rs_k -> bit-identical), stashed in smem past the buffers.
// ---------------------------------------------------------------------------
__global__ __launch_bounds__(256, 2) void gemm_bf16_o(
    const __nv_bfloat16* __restrict__ A, const __nv_bfloat16* __restrict__ Bm,
    float* __restrict__ C, int M, int Nfull, int K,
    const float* __restrict__ gamma, const float* __restrict__ vres,
    const float* __restrict__ partial, long sA, long sB, long sC, long sV)
{
    constexpr int NT = 128, LDA = 36;                 // uint32 pairs per row
    constexpr int BKH = 64;
    constexpr int WMT = 64, WNT = 32, MF = 4, NF = 4;
    constexpr int ASZ = 128 * LDA, BUF = ASZ + NT * LDA;   // uint32 units
    constexpr int RS_OFF = 2 * BUF;                        // rowsum stash

    extern __shared__ uint32_t smu[];
    float* rsm = (float*)(smu + RS_OFF);              // 128 floats
    const int tid = threadIdx.x, wid = tid >> 5, lane = tid & 31;
    const int lr = lane >> 2, lc = lane & 3;
    const int bz = blockIdx.z;

    A  += (size_t)bz * sA;
    Bm += (size_t)bz * sB;
    float* Cb = C + (size_t)bz * sC;
    const float* vres_b = vres + (size_t)bz * sV;

    const int m0 = blockIdx.y * 128, n0 = blockIdx.x * NT;
    const int wm = wid & 1, wn = wid >> 1;
    const uint32_t sbase = smem_u32(smu);

    const int a_row = wm * WMT + (lane & 15);
    const uint32_t a_off0 = (uint32_t)a_row * (LDA * 4) + ((lane >> 4) * 16);
    const int b_row = wn * WNT + (((lane >> 4) & 1) * 8) + (lane & 7);
    const uint32_t b_off0 = (uint32_t)(ASZ * 4) + (uint32_t)b_row * (LDA * 4) +
                            (((lane >> 3) & 1) * 16);

    float acc[MF][NF][4];
#pragma unroll
    for (int i = 0; i < MF; i++)
#pragma unroll
        for (int j = 0; j < NF; j++)
#pragma unroll
            for (int r = 0; r < 4; r++) acc[i][j][r] = 0.f;

    auto stage = [&](int k0, int buf) {
#pragma unroll
        for (int l = 0; l < 4; l++) {
            int idx = tid + l * 256;
            int r = idx >> 3, q = idx & 7;
            CP16(sbase + (uint32_t)(buf * BUF + r * LDA + q * 4) * 4,
                 A + (size_t)(m0 + r) * K + k0 + q * 8);
        }
#pragma unroll
        for (int l = 0; l < 4; l++) {
            int idx = tid + l * 256;
            int r = idx >> 3, q = idx & 7;
            CP16(sbase + (uint32_t)(buf * BUF + ASZ + r * LDA + q * 4) * 4,
                 Bm + (size_t)(n0 + r) * K + k0 + q * 8);
        }
        CP_COMMIT();
    };

    const int T = K / BKH;
    stage(0, 0);

    // Rowsum for this CTA's 128 rows (overlaps with stage-0 cp.async).
    // Same nt-order as the old reduce_rs_k -> bit-identical fp32 sums.
    if (tid < 128) {
        const int gidx = bz * 4096 + m0 + tid;
        float s = 0.f;
#pragma unroll
        for (int nt = 0; nt < 32; nt++) s += partial[(size_t)nt * M_TOT + gidx];
        rsm[tid] = s;
    }

    for (int t = 0; t < T; t++) {
        if (t + 1 < T) { stage((t + 1) * BKH, (t + 1) & 1); CP_WAIT1(); }
        else            { CP_WAIT0(); }
        __syncthreads();

        const uint32_t bufbase = sbase + (uint32_t)((t & 1) * BUF) * 4;
#pragma unroll
        for (int ks = 0; ks < 4; ks++) {      // 4 k16 steps per tile
            uint32_t a[MF][4], b[NF][2];
#pragma unroll
            for (int mf = 0; mf < MF; mf++)
                LDSM_X4(a[mf][0], a[mf][1], a[mf][2], a[mf][3],
                        bufbase + a_off0 + (uint32_t)(mf * 16 * LDA * 4) + ks * 32);
#pragma unroll
            for (int np = 0; np < 2; np++)
                LDSM_X4(b[2 * np][0], b[2 * np][1], b[2 * np + 1][0], b[2 * np + 1][1],
                        bufbase + b_off0 + (uint32_t)(np * 16 * LDA * 4) + ks * 32);
#pragma unroll
            for (int mf = 0; mf < MF; mf++)
#pragma unroll
                for (int nf = 0; nf < NF; nf++)
                    mma_bf16(acc[mf][nf], a[mf], b[nf]);
        }
        __syncthreads();
    }

    const int mb = m0 + wm * WMT, nb = n0 + wn * WNT;
#pragma unroll
    for (int mf = 0; mf < MF; mf++) {
        const int gr0 = mb + mf * 16 + lr, gr1 = gr0 + 8;
        const int rl0 = wm * WMT + mf * 16 + lr;
        const float inv0 = 1.f / rsm[rl0], inv1 = 1.f / rsm[rl0 + 8];
#pragma unroll
        for (int nf = 0; nf < NF; nf++) {
            const int gc = nb + nf * 8 + 2 * lc;
            const float* d = acc[mf][nf];
            float2 vr0 = *reinterpret_cast<const float2*>(&vres_b[(size_t)gr0 * Nfull + gc]);
            float2 vr1 = *reinterpret_cast<const float2*>(&vres_b[(size_t)gr1 * Nfull + gc]);
            float2 gg  = *reinterpret_cast<const float2*>(&gamma[gc]);
            *reinterpret_cast<float2*>(&Cb[(size_t)gr0 * Nfull + gc]) =
                make_float2(fmaf(gg.x, d[0] * inv0, vr0.x), fmaf(gg.y, d[1] * inv0, vr0.y));
            *reinterpret_cast<float2*>(&Cb[(size_t)gr1 * Nfull + gc]) =
                make_float2(fmaf(gg.x, d[2] * inv1, vr1.x), fmaf(gg.y, d[3] * inv1, vr1.y));
        }
    }
}

// ---------------------------------------------------------------------------
// Small kernels
// ---------------------------------------------------------------------------
__global__ void transpose_k(const float* __restrict__ in, float* __restrict__ out,
                            int R, int Ccols)
{
    __shared__ float t[32][33];
    const int c0 = blockIdx.x * 32, r0 = blockIdx.y * 32;
    const int x = threadIdx.x, y = threadIdx.y;
#pragma unroll
    for (int i = 0; i < 32; i += 8)
        t[y + i][x] = in[(size_t)(r0 + y + i) * Ccols + c0 + x];
    __syncthreads();
#pragma unroll
    for (int i = 0; i < 32; i += 8)
        out[(size_t)(c0 + y + i) * R + r0 + x] = tf32r(t[x][y + i]);
}

// Transpose two [F,C] weights into stacked wfgT [128,512] in one launch.
__global__ void transpose2_k(const float* __restrict__ inA, const float* __restrict__ inB,
                             float* __restrict__ out, int R, int Ccols)
{
    __shared__ float t[32][33];
    const float* in = blockIdx.z ? inB : inA;
    float* o = out + (size_t)blockIdx.z * Ccols * R;   // slab offset (64*512)
    const int c0 = blockIdx.x * 32, r0 = blockIdx.y * 32;
    const int x = threadIdx.x, y = threadIdx.y;
#pragma unroll
    for (int i = 0; i < 32; i += 8)
        t[y + i][x] = in[(size_t)(r0 + y + i) * Ccols + c0 + x];
    __syncthreads();
#pragma unroll
    for (int i = 0; i < 32; i += 8)
        o[(size_t)(c0 + y + i) * R + r0 + x] = tf32r(t[x][y + i]);
}

// bias concat + maxg zero, one launch
__global__ void prep_k(const float* __restrict__ a, const float* __restrict__ b,
                       float* __restrict__ out, int* __restrict__ mg)
{
    int t = threadIdx.x;
    out[t] = (t < 64) ? a[t] : b[t - 64];
    if (t < B_) mg[t] = 0;
}

// ---------------------------------------------------------------------------
extern "C" void kernel_launch(void* const* d_in, const int* in_sizes, int n_in,
                              void* d_out, int out_size)
{
    const float* V  = (const float*)d_in[0];
    const float* Wf = (const float*)d_in[1];
    const float* bf = (const float*)d_in[2];
    const float* Wg = (const float*)d_in[3];
    const float* bg = (const float*)d_in[4];
    const float* Wh = (const float*)d_in[5];
    const float* bh = (const float*)d_in[6];
    const float* gm = (const float*)d_in[7];
    float* out = (float*)d_out;

    float *fgP, *partP, *normfP, *bfgP, *wfgT, *whT;
    int* maxgP;
    __nv_bfloat16 *hTP, *pP;
    cudaGetSymbolAddress((void**)&fgP,   g_fg);
    cudaGetSymbolAddress((void**)&hTP,   g_hT);
    cudaGetSymbolAddress((void**)&pP,    g_p);
    cudaGetSymbolAddress((void**)&partP, g_part);
    cudaGetSymbolAddress((void**)&normfP,g_normf);
    cudaGetSymbolAddress((void**)&maxgP, g_maxg);
    cudaGetSymbolAddress((void**)&bfgP,  g_bfg);
    cudaGetSymbolAddress((void**)&wfgT,  g_wfgT);
    cudaGetSymbolAddress((void**)&whT,   g_whT);

    const int SM_TF = 2 * (128 + 128) * 36 * 4;       // 73728 B
    const int SM_BF = 2 * (128 + 128) * 36 * 4 + 512; // 74240 B (+rowsum stash)

    cudaFuncSetAttribute(gemm_tf32<128, 7, true>,
                         cudaFuncAttributeMaxDynamicSharedMemorySize, SM_TF);
    cudaFuncSetAttribute(gemm_tf32<128, 5, true>,
                         cudaFuncAttributeMaxDynamicSharedMemorySize, SM_TF);
    cudaFuncSetAttribute(gemm_tf32<128, 6, false>,
                         cudaFuncAttributeMaxDynamicSharedMemorySize, SM_TF);
    cudaFuncSetAttribute(gemm_bf16_o,
                         cudaFuncAttributeMaxDynamicSharedMemorySize, SM_BF);

    dim3 blk(256);
    dim3 tb(32, 8);

    // Stacked [WfT; WgT] -> wfgT (one launch, z=2); whT; bias concat + maxg=0.
    transpose2_k<<<dim3(C_ / 32, F_ / 32, 2), tb>>>(Wf, Wg, wfgT, F_, C_);
    transpose_k<<<dim3(F_ / 32, F_ / 32), tb>>>(Wh, whT, F_, F_);
    prep_k<<<1, 128>>>(bf, bg, bfgP, maxgP);

    // fg = relu(V @ [Wf|Wg] + [bf|bg]) + fused row norms (normf, maxg)
    gemm_tf32<128, 7, true><<<dim3(1, 128, 1), blk, SM_TF>>>(
        V, wfgT, fgP, M_TOT, 128, F_, F_, F_, bfgP,
        nullptr, maxgP, normfP, 0, 0, 0);

    // hT[b][f][n] = bf16(relu(V@Wh+bh)) transposed per batch
    gemm_tf32<128, 5, true><<<dim3(4, 128, 1), blk, SM_TF>>>(
        V, whT, (float*)hTP, M_TOT, F_, F_, F_, F_, bh,
        nullptr, nullptr, nullptr, 0, 0, 0);

    // scores + fused exp: p = bf16(exp(f@g^T - M_row)), partial rowsums
    gemm_tf32<128, 6, false><<<dim3(32, 32, B_), blk, SM_TF>>>(
        fgP, fgP + 64, (float*)pP, N_, N_, C_, 128, 128, nullptr,
        normfP, maxgP, partP,
        (long)N_ * 128, (long)N_ * 128, (long)N_ * N_);

    // out = gamma * (p @ h / rowsum) + V   (rowsum folded into prologue)
    gemm_bf16_o<<<dim3(4, 32, B_), blk, SM_BF>>>(
        pP, hTP, out, N_, F_, N_, gm, V, partP,
        (long)N_ * N_, (long)F_ * N_, (long)N_ * F_, (long)N_ * F_);
}